// round 6
// baseline (speedup 1.0000x reference)
#include <cuda_runtime.h>
#include <cuda_bf16.h>
#include <cstdint>

// Problem constants
#define BB 2
#define GG 2048
#define HH 4
#define DD 128
#define KDIM 32
#define EE 128

#define TQ 32      // q rows per block
#define TP 32      // p columns per tile
#define NTHREADS 256

// ---------------- device scratch (static allocation is allowed) ----------------
__device__ float g_Q[BB * GG * 128];      // [b][g][h*32+k]
__device__ float g_K[BB * GG * 128];
__device__ float g_V[BB * GG * 128];
__device__ float g_heads[BB * GG * 128];  // [b][g][h*32+v]

// =============================================================================
// K0: fused QKV projection.  Q[h,b,g,k] = sum_d h[b,g,d] * Wq[h,d,k]
// grid = 512 blocks (8 rows each), 128 threads (thread = h*32+k output column)
// =============================================================================
__global__ void qkv_kernel(const float* __restrict__ hin,
                           const float* __restrict__ Wq,
                           const float* __restrict__ Wk,
                           const float* __restrict__ Wv)
{
    __shared__ float hs[8 * 128];
    const int tid  = threadIdx.x;
    const int row0 = blockIdx.x * 8;

    for (int idx = tid; idx < 8 * 128; idx += 128)
        hs[idx] = hin[(size_t)row0 * 128 + idx];
    __syncthreads();

    const int hh = tid >> 5;
    const int k  = tid & 31;

    float aq[8], ak[8], av[8];
#pragma unroll
    for (int r = 0; r < 8; r++) { aq[r] = 0.f; ak[r] = 0.f; av[r] = 0.f; }

    for (int d = 0; d < 128; d++) {
        const int wi = (hh * 128 + d) * 32 + k;
        const float wq = __ldg(Wq + wi);
        const float wk = __ldg(Wk + wi);
        const float wv = __ldg(Wv + wi);
#pragma unroll
        for (int r = 0; r < 8; r++) {
            const float hv = hs[r * 128 + d];   // warp-broadcast LDS
            aq[r] += hv * wq;
            ak[r] += hv * wk;
            av[r] += hv * wv;
        }
    }
#pragma unroll
    for (int r = 0; r < 8; r++) {
        const size_t o = (size_t)(row0 + r) * 128 + tid;
        g_Q[o] = aq[r];
        g_K[o] = ak[r];
        g_V[o] = av[r];
    }
}

// =============================================================================
// K1: fused scores + per-score MLP + online softmax + A@V  (+ osa pass-through)
//
// grid = (G/TQ, B) = (64, 2), block = 256 threads = 8 warps.
// Warp w owns q-rows [blk*32 + 4w .. +3].  Lane = p inside the tile for
// scores/MLP/softmax; lane = v for the AV accumulation (acc kept in regs).
// Shared (dynamic, 67584 B):
//   Qs[32][132], Ks[32][132], Vs[32][132]  (pad=4 -> conflict-free f4 LDS)
//   ws[8 warps][512]  exp-weight staging  (per-warp, syncwarp only)
//   wts[128]          MLP weights (w1|b1|w2|b2)
// =============================================================================
__device__ __forceinline__ float f4get(const float4& v, int c) {
    return c == 0 ? v.x : c == 1 ? v.y : c == 2 ? v.z : v.w;
}

#define SM_QS 0
#define SM_KS 4224
#define SM_VS 8448
#define SM_WS 12672
#define SM_WT 16768
#define SMEM_FLOATS 16896
#define SMEM_BYTES (SMEM_FLOATS * 4)

__global__ __launch_bounds__(NTHREADS, 1)
void attn_kernel(const float* __restrict__ osa,
                 const float* __restrict__ w1,
                 const float* __restrict__ b1,
                 const float* __restrict__ w2,
                 const float* __restrict__ b2,
                 float* __restrict__ osaCopy,   // nullptr if output has no osa part
                 int doCopy)
{
    extern __shared__ float sm[];
    float* Qs  = sm + SM_QS;
    float* Ks  = sm + SM_KS;
    float* Vs  = sm + SM_VS;
    float* wsA = sm + SM_WS;
    float* wts = sm + SM_WT;

    const int tid  = threadIdx.x;
    const int warp = tid >> 5;
    const int lane = tid & 31;
    const int b    = blockIdx.y;
    const int q0   = blockIdx.x * TQ;

    // --- load MLP weights into shared ---
    if (tid < 64)        wts[tid] = __ldg(w1 + tid);
    else if (tid < 72)   wts[tid] = __ldg(b1 + (tid - 64));
    else if (tid < 104)  wts[tid] = __ldg(w2 + (tid - 72));
    else if (tid < 108)  wts[tid] = __ldg(b2 + (tid - 104));

    // --- load Q tile (32 rows x 128) into padded shared ---
    {
        const int r  = tid >> 3;          // 0..31
        const int cg = (tid & 7) * 4;     // float4 group
        const float4* src = (const float4*)(g_Q + (size_t)(b * GG + q0 + r) * 128);
        float4* dst = (float4*)(Qs + r * 132);
#pragma unroll
        for (int j = 0; j < 4; j++) dst[cg + j] = __ldg(src + cg + j);
    }

    float s[4][4];                 // scores, reused as MLP logits y
    float acc[4][4];               // AV accumulator, lane = v
    float m[4][4], l[4][4];        // online softmax state (warp-uniform)
#pragma unroll
    for (int q = 0; q < 4; q++)
#pragma unroll
        for (int h = 0; h < 4; h++) { acc[q][h] = 0.f; m[q][h] = -1e30f; l[q][h] = 0.f; }

    float* ws = wsA + warp * 512;
    const int qw = warp * 4;

    __syncthreads();

    for (int pt = 0; pt < GG / TP; pt++) {
        const int pg0 = pt * TP;

        // ---- prefetch osa (in flight across the tile load + scores) ----
        float o[4][4];
#pragma unroll
        for (int q = 0; q < 4; q++) {
            const int qg = q0 + qw + q;
#pragma unroll
            for (int h = 0; h < 4; h++) {
                const size_t idx = ((size_t)(h * BB + b) * GG + qg) * GG + pg0 + lane;
                o[q][h] = __ldg(osa + idx);
            }
        }

        __syncthreads();   // previous tile fully consumed by all warps

        // ---- stage K and V tiles ----
        {
            const int r  = tid >> 3;
            const int cg = (tid & 7) * 4;
            const float4* srcK = (const float4*)(g_K + (size_t)(b * GG + pg0 + r) * 128);
            const float4* srcV = (const float4*)(g_V + (size_t)(b * GG + pg0 + r) * 128);
            float4* dK = (float4*)(Ks + r * 132);
            float4* dV = (float4*)(Vs + r * 132);
#pragma unroll
            for (int j = 0; j < 4; j++) {
                dK[cg + j] = __ldg(srcK + cg + j);
                dV[cg + j] = __ldg(srcV + cg + j);
            }
        }
        __syncthreads();

        // ---- scores: lane = p.  s[q][h] = Q[q,h,:].K[p,h,:] ----
        const float4* kRow = (const float4*)(Ks + lane * 132);
#pragma unroll
        for (int q = 0; q < 4; q++)
#pragma unroll
            for (int h = 0; h < 4; h++) s[q][h] = 0.f;

#pragma unroll
        for (int h = 0; h < 4; h++) {
#pragma unroll
            for (int ig2 = 0; ig2 < 8; ig2++) {
                const int ig = h * 8 + ig2;
                const float4 k4 = kRow[ig];
#pragma unroll
                for (int q = 0; q < 4; q++) {
                    const float4 q4 = ((const float4*)(Qs + (qw + q) * 132))[ig];
                    s[q][h] += q4.x * k4.x + q4.y * k4.y + q4.z * k4.z + q4.w * k4.w;
                }
            }
        }

        // ---- osa pass-through copy to output ----
        if (doCopy) {
#pragma unroll
            for (int q = 0; q < 4; q++) {
                const int qg = q0 + qw + q;
#pragma unroll
                for (int h = 0; h < 4; h++) {
                    const size_t idx = ((size_t)(h * BB + b) * GG + qg) * GG + pg0 + lane;
                    osaCopy[idx] = o[q][h];
                }
            }
        }

        // ---- per-score MLP: x = [s0..s3, o0..o3] -> y[4] (overwrites s) ----
#pragma unroll
        for (int q = 0; q < 4; q++) {
            float hid[8];
#pragma unroll
            for (int j = 0; j < 8; j++) {
                float z = wts[64 + j];
#pragma unroll
                for (int i = 0; i < 4; i++) z += wts[j * 8 + i] * s[q][i];
#pragma unroll
                for (int i = 0; i < 4; i++) z += wts[j * 8 + 4 + i] * o[q][i];
                hid[j] = fmaxf(z, 0.f);
            }
            float y[4];
#pragma unroll
            for (int h = 0; h < 4; h++) {
                float z = wts[104 + h];
#pragma unroll
                for (int j = 0; j < 8; j++) z += wts[72 + h * 8 + j] * hid[j];
                y[h] = z;
            }
#pragma unroll
            for (int h = 0; h < 4; h++) s[q][h] = y[h];
        }

        // ---- online softmax update (per q,h); stage exp weights to shared ----
#pragma unroll
        for (int q = 0; q < 4; q++) {
#pragma unroll
            for (int h = 0; h < 4; h++) {
                const float y = s[q][h];
                float tmax = y;
#pragma unroll
                for (int off = 16; off; off >>= 1)
                    tmax = fmaxf(tmax, __shfl_xor_sync(0xffffffffu, tmax, off));
                const float mn = fmaxf(m[q][h], tmax);
                const float w  = __expf(y - mn);
                float tsum = w;
#pragma unroll
                for (int off = 16; off; off >>= 1)
                    tsum += __shfl_xor_sync(0xffffffffu, tsum, off);
                const float corr = __expf(m[q][h] - mn);
                l[q][h] = l[q][h] * corr + tsum;
                m[q][h] = mn;
                acc[q][h] *= corr;
                ws[(q * 4 + h) * 32 + lane] = w;
            }
        }
        __syncwarp();

        // ---- AV: lane = v.  acc[q][h] += sum_p w[q][h][p] * V[p][h*32+v] ----
#pragma unroll
        for (int h = 0; h < 4; h++) {
#pragma unroll
            for (int pg = 0; pg < 8; pg++) {
                const float4 wq0 = ((const float4*)(ws + (0 * 4 + h) * 32))[pg];
                const float4 wq1 = ((const float4*)(ws + (1 * 4 + h) * 32))[pg];
                const float4 wq2 = ((const float4*)(ws + (2 * 4 + h) * 32))[pg];
                const float4 wq3 = ((const float4*)(ws + (3 * 4 + h) * 32))[pg];
#pragma unroll
                for (int c = 0; c < 4; c++) {
                    const float vv = Vs[(pg * 4 + c) * 132 + h * 32 + lane];
                    acc[0][h] += f4get(wq0, c) * vv;
                    acc[1][h] += f4get(wq1, c) * vv;
                    acc[2][h] += f4get(wq2, c) * vv;
                    acc[3][h] += f4get(wq3, c) * vv;
                }
            }
        }
        __syncwarp();   // ws reused next tile
    }

    // ---- epilogue: normalized heads -> scratch (lane = v) ----
#pragma unroll
    for (int q = 0; q < 4; q++) {
        const int qg = q0 + qw + q;
#pragma unroll
        for (int h = 0; h < 4; h++) {
            g_heads[(size_t)(b * GG + qg) * 128 + h * 32 + lane] = acc[q][h] / l[q][h];
        }
    }
}

// =============================================================================
// K3: out[b,q,e] = sum_{h,v} heads[b,q,h*32+v] * Wout[h,v,e]
//     Wout is (H,KD,E) contiguous == flat [t=h*32+v][e], so plain 4096x128x128.
// =============================================================================
__global__ void outproj_kernel(const float* __restrict__ Wout,
                               float* __restrict__ out)
{
    __shared__ float hs[8 * 128];
    const int tid  = threadIdx.x;     // e (0..127)
    const int row0 = blockIdx.x * 8;

    for (int idx = tid; idx < 8 * 128; idx += 128)
        hs[idx] = g_heads[(size_t)row0 * 128 + idx];
    __syncthreads();

    float a[8];
#pragma unroll
    for (int r = 0; r < 8; r++) a[r] = 0.f;

    for (int t = 0; t < 128; t++) {
        const float w = __ldg(Wout + t * 128 + tid);
#pragma unroll
        for (int r = 0; r < 8; r++) a[r] += hs[r * 128 + t] * w;
    }
#pragma unroll
    for (int r = 0; r < 8; r++)
        out[(size_t)(row0 + r) * 128 + tid] = a[r];
}

// =============================================================================
extern "C" void kernel_launch(void* const* d_in, const int* in_sizes, int n_in,
                              void* d_out, int out_size)
{
    const float* hin  = (const float*)d_in[0];   // (B,G,D)
    const float* osa  = (const float*)d_in[1];   // (H,B,G,G)
    const float* Wq   = (const float*)d_in[2];
    const float* Wk   = (const float*)d_in[3];
    const float* Wv   = (const float*)d_in[4];
    const float* Wout = (const float*)d_in[5];
    const float* w1   = (const float*)d_in[6];
    const float* b1   = (const float*)d_in[7];
    const float* w2   = (const float*)d_in[8];
    const float* b2   = (const float*)d_in[9];
    (void)in_sizes; (void)n_in;

    float* out = (float*)d_out;

    const int OUT_ELEMS = BB * GG * EE;                       // 524288
    const long long OSA_ELEMS = (long long)HH * BB * GG * GG; // 33554432
    const int doCopy = ((long long)out_size >= OUT_ELEMS + OSA_ELEMS) ? 1 : 0;
    float* osaCopy = doCopy ? (out + OUT_ELEMS) : out;        // dummy if unused

    cudaFuncSetAttribute(attn_kernel,
                         cudaFuncAttributeMaxDynamicSharedMemorySize, SMEM_BYTES);

    qkv_kernel<<<BB * GG / 8, 128>>>(hin, Wq, Wk, Wv);
    attn_kernel<<<dim3(GG / TQ, BB), NTHREADS, SMEM_BYTES>>>(
        osa, w1, b1, w2, b2, osaCopy, doCopy);
    outproj_kernel<<<BB * GG / 8, 128>>>(Wout, out);
}

// round 7
// speedup vs baseline: 1.0009x; 1.0009x over previous
#include <cuda_runtime.h>
#include <cuda_bf16.h>
#include <cstdint>

// Problem constants
#define BB 2
#define GG 2048
#define HH 4
#define DD 128
#define KDIM 32
#define EE 128

#define TQ 32      // q rows per block
#define TP 32      // p columns per tile
#define NTHREADS 256

// ---------------- device scratch (static allocation is allowed) ----------------
__device__ float g_Q[BB * GG * 128];      // [b][g][h*32+k]
__device__ float g_K[BB * GG * 128];
__device__ float g_V[BB * GG * 128];
__device__ float g_heads[BB * GG * 128];  // [b][g][h*32+v]

// =============================================================================
// K0: fused QKV projection.  Q[h,b,g,k] = sum_d h[b,g,d] * Wq[h,d,k]
// grid = 512 blocks (8 rows each), 128 threads (thread = h*32+k output column)
// =============================================================================
__global__ void qkv_kernel(const float* __restrict__ hin,
                           const float* __restrict__ Wq,
                           const float* __restrict__ Wk,
                           const float* __restrict__ Wv)
{
    __shared__ float hs[8 * 128];
    const int tid  = threadIdx.x;
    const int row0 = blockIdx.x * 8;

    for (int idx = tid; idx < 8 * 128; idx += 128)
        hs[idx] = hin[(size_t)row0 * 128 + idx];
    __syncthreads();

    const int hh = tid >> 5;
    const int k  = tid & 31;

    float aq[8], ak[8], av[8];
#pragma unroll
    for (int r = 0; r < 8; r++) { aq[r] = 0.f; ak[r] = 0.f; av[r] = 0.f; }

    for (int d = 0; d < 128; d++) {
        const int wi = (hh * 128 + d) * 32 + k;
        const float wq = __ldg(Wq + wi);
        const float wk = __ldg(Wk + wi);
        const float wv = __ldg(Wv + wi);
#pragma unroll
        for (int r = 0; r < 8; r++) {
            const float hv = hs[r * 128 + d];   // warp-broadcast LDS
            aq[r] += hv * wq;
            ak[r] += hv * wk;
            av[r] += hv * wv;
        }
    }
#pragma unroll
    for (int r = 0; r < 8; r++) {
        const size_t o = (size_t)(row0 + r) * 128 + tid;
        g_Q[o] = aq[r];
        g_K[o] = ak[r];
        g_V[o] = av[r];
    }
}

// =============================================================================
// K1: fused scores + per-score MLP + online softmax + A@V  (+ osa pass-through)
//
// grid = (G/TQ, B) = (64, 2), block = 256 threads = 8 warps.
// Warp w owns q-rows [blk*32 + 4w .. +3].  Lane = p inside the tile for
// scores/MLP/softmax; lane = v for the AV accumulation (acc kept in regs).
// Shared (dynamic, 67584 B):
//   Qs[32][132], Ks[32][132], Vs[32][132]  (pad=4 -> conflict-free f4 LDS)
//   ws[8 warps][512]  exp-weight staging  (per-warp, syncwarp only)
//   wts[128]          MLP weights (w1|b1|w2|b2)
// =============================================================================
__device__ __forceinline__ float f4get(const float4& v, int c) {
    return c == 0 ? v.x : c == 1 ? v.y : c == 2 ? v.z : v.w;
}

#define SM_QS 0
#define SM_KS 4224
#define SM_VS 8448
#define SM_WS 12672
#define SM_WT 16768
#define SMEM_FLOATS 16896
#define SMEM_BYTES (SMEM_FLOATS * 4)

__global__ __launch_bounds__(NTHREADS, 1)
void attn_kernel(const float* __restrict__ osa,
                 const float* __restrict__ w1,
                 const float* __restrict__ b1,
                 const float* __restrict__ w2,
                 const float* __restrict__ b2,
                 float* __restrict__ osaCopy,   // nullptr if output has no osa part
                 int doCopy)
{
    extern __shared__ float sm[];
    float* Qs  = sm + SM_QS;
    float* Ks  = sm + SM_KS;
    float* Vs  = sm + SM_VS;
    float* wsA = sm + SM_WS;
    float* wts = sm + SM_WT;

    const int tid  = threadIdx.x;
    const int warp = tid >> 5;
    const int lane = tid & 31;
    const int b    = blockIdx.y;
    const int q0   = blockIdx.x * TQ;

    // --- load MLP weights into shared ---
    if (tid < 64)        wts[tid] = __ldg(w1 + tid);
    else if (tid < 72)   wts[tid] = __ldg(b1 + (tid - 64));
    else if (tid < 104)  wts[tid] = __ldg(w2 + (tid - 72));
    else if (tid < 108)  wts[tid] = __ldg(b2 + (tid - 104));

    // --- load Q tile (32 rows x 128) into padded shared ---
    {
        const int r  = tid >> 3;          // 0..31
        const int cg = (tid & 7) * 4;     // float4 group
        const float4* src = (const float4*)(g_Q + (size_t)(b * GG + q0 + r) * 128);
        float4* dst = (float4*)(Qs + r * 132);
#pragma unroll
        for (int j = 0; j < 4; j++) dst[cg + j] = __ldg(src + cg + j);
    }

    float s[4][4];                 // scores, reused as MLP logits y
    float acc[4][4];               // AV accumulator, lane = v
    float m[4][4], l[4][4];        // online softmax state (warp-uniform)
#pragma unroll
    for (int q = 0; q < 4; q++)
#pragma unroll
        for (int h = 0; h < 4; h++) { acc[q][h] = 0.f; m[q][h] = -1e30f; l[q][h] = 0.f; }

    float* ws = wsA + warp * 512;
    const int qw = warp * 4;

    __syncthreads();

    for (int pt = 0; pt < GG / TP; pt++) {
        const int pg0 = pt * TP;

        // ---- prefetch osa (in flight across the tile load + scores) ----
        float o[4][4];
#pragma unroll
        for (int q = 0; q < 4; q++) {
            const int qg = q0 + qw + q;
#pragma unroll
            for (int h = 0; h < 4; h++) {
                const size_t idx = ((size_t)(h * BB + b) * GG + qg) * GG + pg0 + lane;
                o[q][h] = __ldg(osa + idx);
            }
        }

        __syncthreads();   // previous tile fully consumed by all warps

        // ---- stage K and V tiles ----
        {
            const int r  = tid >> 3;
            const int cg = (tid & 7) * 4;
            const float4* srcK = (const float4*)(g_K + (size_t)(b * GG + pg0 + r) * 128);
            const float4* srcV = (const float4*)(g_V + (size_t)(b * GG + pg0 + r) * 128);
            float4* dK = (float4*)(Ks + r * 132);
            float4* dV = (float4*)(Vs + r * 132);
#pragma unroll
            for (int j = 0; j < 4; j++) {
                dK[cg + j] = __ldg(srcK + cg + j);
                dV[cg + j] = __ldg(srcV + cg + j);
            }
        }
        __syncthreads();

        // ---- scores: lane = p.  s[q][h] = Q[q,h,:].K[p,h,:] ----
        const float4* kRow = (const float4*)(Ks + lane * 132);
#pragma unroll
        for (int q = 0; q < 4; q++)
#pragma unroll
            for (int h = 0; h < 4; h++) s[q][h] = 0.f;

#pragma unroll
        for (int h = 0; h < 4; h++) {
#pragma unroll
            for (int ig2 = 0; ig2 < 8; ig2++) {
                const int ig = h * 8 + ig2;
                const float4 k4 = kRow[ig];
#pragma unroll
                for (int q = 0; q < 4; q++) {
                    const float4 q4 = ((const float4*)(Qs + (qw + q) * 132))[ig];
                    s[q][h] += q4.x * k4.x + q4.y * k4.y + q4.z * k4.z + q4.w * k4.w;
                }
            }
        }

        // ---- osa pass-through copy to output ----
        if (doCopy) {
#pragma unroll
            for (int q = 0; q < 4; q++) {
                const int qg = q0 + qw + q;
#pragma unroll
                for (int h = 0; h < 4; h++) {
                    const size_t idx = ((size_t)(h * BB + b) * GG + qg) * GG + pg0 + lane;
                    osaCopy[idx] = o[q][h];
                }
            }
        }

        // ---- per-score MLP: x = [s0..s3, o0..o3] -> y[4] (overwrites s) ----
#pragma unroll
        for (int q = 0; q < 4; q++) {
            float hid[8];
#pragma unroll
            for (int j = 0; j < 8; j++) {
                float z = wts[64 + j];
#pragma unroll
                for (int i = 0; i < 4; i++) z += wts[j * 8 + i] * s[q][i];
#pragma unroll
                for (int i = 0; i < 4; i++) z += wts[j * 8 + 4 + i] * o[q][i];
                hid[j] = fmaxf(z, 0.f);
            }
            float y[4];
#pragma unroll
            for (int h = 0; h < 4; h++) {
                float z = wts[104 + h];
#pragma unroll
                for (int j = 0; j < 8; j++) z += wts[72 + h * 8 + j] * hid[j];
                y[h] = z;
            }
#pragma unroll
            for (int h = 0; h < 4; h++) s[q][h] = y[h];
        }

        // ---- online softmax update (per q,h); stage exp weights to shared ----
#pragma unroll
        for (int q = 0; q < 4; q++) {
#pragma unroll
            for (int h = 0; h < 4; h++) {
                const float y = s[q][h];
                float tmax = y;
#pragma unroll
                for (int off = 16; off; off >>= 1)
                    tmax = fmaxf(tmax, __shfl_xor_sync(0xffffffffu, tmax, off));
                const float mn = fmaxf(m[q][h], tmax);
                const float w  = __expf(y - mn);
                float tsum = w;
#pragma unroll
                for (int off = 16; off; off >>= 1)
                    tsum += __shfl_xor_sync(0xffffffffu, tsum, off);
                const float corr = __expf(m[q][h] - mn);
                l[q][h] = l[q][h] * corr + tsum;
                m[q][h] = mn;
                acc[q][h] *= corr;
                ws[(q * 4 + h) * 32 + lane] = w;
            }
        }
        __syncwarp();

        // ---- AV: lane = v.  acc[q][h] += sum_p w[q][h][p] * V[p][h*32+v] ----
#pragma unroll
        for (int h = 0; h < 4; h++) {
#pragma unroll
            for (int pg = 0; pg < 8; pg++) {
                const float4 wq0 = ((const float4*)(ws + (0 * 4 + h) * 32))[pg];
                const float4 wq1 = ((const float4*)(ws + (1 * 4 + h) * 32))[pg];
                const float4 wq2 = ((const float4*)(ws + (2 * 4 + h) * 32))[pg];
                const float4 wq3 = ((const float4*)(ws + (3 * 4 + h) * 32))[pg];
#pragma unroll
                for (int c = 0; c < 4; c++) {
                    const float vv = Vs[(pg * 4 + c) * 132 + h * 32 + lane];
                    acc[0][h] += f4get(wq0, c) * vv;
                    acc[1][h] += f4get(wq1, c) * vv;
                    acc[2][h] += f4get(wq2, c) * vv;
                    acc[3][h] += f4get(wq3, c) * vv;
                }
            }
        }
        __syncwarp();   // ws reused next tile
    }

    // ---- epilogue: normalized heads -> scratch (lane = v) ----
#pragma unroll
    for (int q = 0; q < 4; q++) {
        const int qg = q0 + qw + q;
#pragma unroll
        for (int h = 0; h < 4; h++) {
            g_heads[(size_t)(b * GG + qg) * 128 + h * 32 + lane] = acc[q][h] / l[q][h];
        }
    }
}

// =============================================================================
// K3: out[b,q,e] = sum_{h,v} heads[b,q,h*32+v] * Wout[h,v,e]
//     Wout is (H,KD,E) contiguous == flat [t=h*32+v][e], so plain 4096x128x128.
// =============================================================================
__global__ void outproj_kernel(const float* __restrict__ Wout,
                               float* __restrict__ out)
{
    __shared__ float hs[8 * 128];
    const int tid  = threadIdx.x;     // e (0..127)
    const int row0 = blockIdx.x * 8;

    for (int idx = tid; idx < 8 * 128; idx += 128)
        hs[idx] = g_heads[(size_t)row0 * 128 + idx];
    __syncthreads();

    float a[8];
#pragma unroll
    for (int r = 0; r < 8; r++) a[r] = 0.f;

    for (int t = 0; t < 128; t++) {
        const float w = __ldg(Wout + t * 128 + tid);
#pragma unroll
        for (int r = 0; r < 8; r++) a[r] += hs[r * 128 + t] * w;
    }
#pragma unroll
    for (int r = 0; r < 8; r++)
        out[(size_t)(row0 + r) * 128 + tid] = a[r];
}

// =============================================================================
extern "C" void kernel_launch(void* const* d_in, const int* in_sizes, int n_in,
                              void* d_out, int out_size)
{
    const float* hin  = (const float*)d_in[0];   // (B,G,D)
    const float* osa  = (const float*)d_in[1];   // (H,B,G,G)
    const float* Wq   = (const float*)d_in[2];
    const float* Wk   = (const float*)d_in[3];
    const float* Wv   = (const float*)d_in[4];
    const float* Wout = (const float*)d_in[5];
    const float* w1   = (const float*)d_in[6];
    const float* b1   = (const float*)d_in[7];
    const float* w2   = (const float*)d_in[8];
    const float* b2   = (const float*)d_in[9];
    (void)in_sizes; (void)n_in;

    float* out = (float*)d_out;

    const int OUT_ELEMS = BB * GG * EE;                       // 524288
    const long long OSA_ELEMS = (long long)HH * BB * GG * GG; // 33554432
    const int doCopy = ((long long)out_size >= OUT_ELEMS + OSA_ELEMS) ? 1 : 0;
    float* osaCopy = doCopy ? (out + OUT_ELEMS) : out;        // dummy if unused

    cudaFuncSetAttribute(attn_kernel,
                         cudaFuncAttributeMaxDynamicSharedMemorySize, SMEM_BYTES);

    qkv_kernel<<<BB * GG / 8, 128>>>(hin, Wq, Wk, Wv);
    attn_kernel<<<dim3(GG / TQ, BB), NTHREADS, SMEM_BYTES>>>(
        osa, w1, b1, w2, b2, osaCopy, doCopy);
    outproj_kernel<<<BB * GG / 8, 128>>>(Wout, out);
}

// round 8
// speedup vs baseline: 1.0493x; 1.0484x over previous
#include <cuda_runtime.h>
#include <cuda_bf16.h>
#include <cstdint>

#define BB 2
#define GG 2048
#define HH 4
#define EE 128

#define TQ 32      // q rows per block
#define TP 64      // p columns per tile
#define NT 512     // threads per attn block (16 warps)

// ---------------- device scratch ----------------
__device__ float g_Q[BB * GG * 128];      // [b][g][h*32+k]
__device__ float g_K[BB * GG * 128];      // [b][g][h*32+k]
__device__ float g_Vt[BB * 128 * GG];     // TRANSPOSED: [b][h*32+v][g]
__device__ float g_heads[BB * GG * 128];  // [b][g][h*32+v]

// ---------------- f32x2 helpers ----------------
__device__ __forceinline__ unsigned long long pack2(float a, float b) {
    unsigned long long r;
    asm("mov.b64 %0, {%1, %2};" : "=l"(r) : "f"(a), "f"(b));
    return r;
}
__device__ __forceinline__ void unpack2(unsigned long long v, float& a, float& b) {
    asm("mov.b64 {%0, %1}, %2;" : "=f"(a), "=f"(b) : "l"(v));
}
__device__ __forceinline__ void fma2(unsigned long long& d,
                                     unsigned long long a, unsigned long long b) {
    asm("fma.rn.f32x2 %0, %1, %2, %0;" : "+l"(d) : "l"(a), "l"(b));
}
__device__ __forceinline__ void mul2(unsigned long long& d, unsigned long long a) {
    asm("mul.rn.f32x2 %0, %0, %1;" : "+l"(d) : "l"(a));
}

#define CP_ASYNC16(dst, src) \
    asm volatile("cp.async.cg.shared.global [%0], [%1], 16;" :: "r"(dst), "l"(src))
#define CP_COMMIT() asm volatile("cp.async.commit_group;" ::: "memory")
#define CP_WAIT1()  asm volatile("cp.async.wait_group 1;" ::: "memory")
#define CP_WAIT0()  asm volatile("cp.async.wait_group 0;" ::: "memory")

// =============================================================================
// K0: fused QKV projection; V is written globally transposed (d-major).
// grid = 256 blocks x 16 rows, 256 threads.
// =============================================================================
__global__ void qkv_kernel(const float* __restrict__ hin,
                           const float* __restrict__ Wq,
                           const float* __restrict__ Wk,
                           const float* __restrict__ Wv)
{
    __shared__ float hs[16 * 128];
    const int tid  = threadIdx.x;
    const int row0 = blockIdx.x * 16;

    for (int i = tid; i < 16 * 128; i += 256)
        hs[i] = hin[(size_t)row0 * 128 + i];
    __syncthreads();

    const int sub   = tid >> 7;       // 0/1 -> rows 0-7 / 8-15
    const int col   = tid & 127;      // output dim = h*32+k
    const int rbase = sub * 8;

    float aq[8], ak[8], av[8];
#pragma unroll
    for (int r = 0; r < 8; r++) { aq[r] = 0.f; ak[r] = 0.f; av[r] = 0.f; }

    const int hh = col >> 5, k = col & 31;
    for (int d = 0; d < 128; d++) {
        const int wi = (hh * 128 + d) * 32 + k;
        const float wq = __ldg(Wq + wi);
        const float wk = __ldg(Wk + wi);
        const float wv = __ldg(Wv + wi);
#pragma unroll
        for (int r = 0; r < 8; r++) {
            const float hv = hs[(rbase + r) * 128 + d];
            aq[r] += hv * wq;
            ak[r] += hv * wk;
            av[r] += hv * wv;
        }
    }

    const int growbase = row0 + rbase;
    const int b = growbase >> 11;     // block never straddles batches (16 | 2048)
#pragma unroll
    for (int r = 0; r < 8; r++) {
        const int grow = growbase + r;
        const int g    = grow & 2047;
        g_Q[(size_t)grow * 128 + col] = aq[r];
        g_K[(size_t)grow * 128 + col] = ak[r];
        g_Vt[((size_t)(b * 128 + col)) * 2048 + g] = av[r];
    }
}

// =============================================================================
// K1: fused scores + MLP + online softmax + A@V (+ osa pass-through)
//
// grid = (G/TQ=64, B=2), 512 threads = 16 warps. Warp owns 2 q rows.
// Lane owns p-pair (2*lane, 2*lane+1) of the 64-wide p tile.
// Double-buffered cp.async staging of K (row-permuted) and Vt (d-major).
// =============================================================================
#define SM_QS 0
#define SM_KS 4224              /* 2 x 64x132 */
#define SM_VT 21120             /* 2 x 128x68 */
#define SM_WS 38528             /* 16 warps x 256 ull (as floats: 8192) */
#define SM_WT 46720             /* 108 ull = 216 floats */
#define SMEM_FLOATS 46936
#define SMEM_BYTES (SMEM_FLOATS * 4)
#define KBUF 8448
#define VBUF 8704

__device__ __forceinline__ void stage_cp(uint32_t smaddr, int buf, int b, int pg0, int tid)
{
    // K tile: 64 rows x 128 floats, row p -> smem row perm(p)=(p>>1)+(p&1)*32
    {
        const int r  = tid >> 3;
        const int c0 = (tid & 7) * 16;                 // float offset
        const int pr = (r >> 1) + (r & 1) * 32;
        const float* src = g_K + ((size_t)(b * GG + pg0 + r)) * 128 + c0;
        const uint32_t dst = smaddr + (uint32_t)(SM_KS + buf * KBUF + pr * 132 + c0) * 4u;
#pragma unroll
        for (int j = 0; j < 4; j++)
            CP_ASYNC16(dst + j * 16u, src + j * 4);
    }
    // V tile (d-major): 128 rows x 64 floats
#pragma unroll
    for (int it = 0; it < 4; it++) {
        const int c   = tid + it * 512;
        const int d   = c >> 4;
        const int off = (c & 15) * 4;
        const float* src = g_Vt + ((size_t)(b * 128 + d)) * 2048 + pg0 + off;
        const uint32_t dst = smaddr + (uint32_t)(SM_VT + buf * VBUF + d * 68 + off) * 4u;
        CP_ASYNC16(dst, src);
    }
}

__global__ __launch_bounds__(NT, 1)
void attn_kernel(const float* __restrict__ osa,
                 const float* __restrict__ w1,
                 const float* __restrict__ b1,
                 const float* __restrict__ w2,
                 const float* __restrict__ b2,
                 float* __restrict__ osaCopy,
                 int doCopy)
{
    extern __shared__ float sm[];
    const uint32_t smaddr = (uint32_t)__cvta_generic_to_shared(sm);

    float* Qs = sm + SM_QS;
    unsigned long long* wtU = (unsigned long long*)(sm + SM_WT);

    const int tid  = threadIdx.x;
    const int warp = tid >> 5;
    const int lane = tid & 31;
    const int b    = blockIdx.y;
    const int q0   = blockIdx.x * TQ;
    const int qw   = warp * 2;

    unsigned long long* wsU = (unsigned long long*)(sm + SM_WS) + warp * 256;

    // MLP weights, pre-duplicated {w,w} for f32x2
    if (tid < 108) {
        float v;
        if (tid < 64)       v = __ldg(w1 + tid);
        else if (tid < 72)  v = __ldg(b1 + tid - 64);
        else if (tid < 104) v = __ldg(w2 + tid - 72);
        else                v = __ldg(b2 + tid - 104);
        wtU[tid] = pack2(v, v);
    }

    // Q tile: 32 rows x 128, stride 132
    {
        const int r  = tid >> 4;
        const int c0 = (tid & 15) * 2;
        const float4* src = (const float4*)(g_Q + (size_t)(b * GG + q0 + r) * 128);
        float4* dst = (float4*)(Qs + r * 132);
        dst[c0]     = __ldg(src + c0);
        dst[c0 + 1] = __ldg(src + c0 + 1);
    }

    // prefetch tile 0
    stage_cp(smaddr, 0, b, 0, tid);
    CP_COMMIT();

    unsigned long long acc[2][4];   // packed over p-parity
    float m[2][4], l[2][4];
#pragma unroll
    for (int q = 0; q < 2; q++)
#pragma unroll
        for (int h = 0; h < 4; h++) { acc[q][h] = 0ULL; m[q][h] = -1e30f; l[q][h] = 0.f; }

    for (int pt = 0; pt < GG / TP; pt++) {
        const int pg0 = pt * TP;

        // osa pair loads (LDG.64, p-pair adjacent) — in flight across staging
        unsigned long long o2[2][4];
#pragma unroll
        for (int q = 0; q < 2; q++) {
            const int qg = q0 + qw + q;
#pragma unroll
            for (int h = 0; h < 4; h++) {
                const size_t idx = ((size_t)(h * BB + b) * GG + qg) * GG + pg0 + 2 * lane;
                o2[q][h] = __ldg((const unsigned long long*)(osa + idx));
            }
        }

        __syncthreads();   // previous tile fully consumed -> buffers free

        if (pt + 1 < GG / TP) {
            stage_cp(smaddr, (pt + 1) & 1, b, pg0 + TP, tid);
            CP_COMMIT();
            CP_WAIT1();
        } else {
            CP_WAIT0();
        }
        __syncthreads();   // current buffer visible

        const float* Ks = sm + SM_KS + (pt & 1) * KBUF;
        const float* Vt = sm + SM_VT + (pt & 1) * VBUF;

        // osa pass-through
        if (doCopy) {
#pragma unroll
            for (int q = 0; q < 2; q++) {
                const int qg = q0 + qw + q;
#pragma unroll
                for (int h = 0; h < 4; h++) {
                    const size_t idx = ((size_t)(h * BB + b) * GG + qg) * GG + pg0 + 2 * lane;
                    *(unsigned long long*)(osaCopy + idx) = o2[q][h];
                }
            }
        }

        // ---- scores: packed over d-pairs. Row lane = p0=2*lane, row lane+32 = p1 ----
        float s0[2][4], s1[2][4];
        {
            const ulonglong2* kR0 = (const ulonglong2*)(Ks + lane * 132);
            const ulonglong2* kR1 = (const ulonglong2*)(Ks + (lane + 32) * 132);
            const ulonglong2* qA  = (const ulonglong2*)(Qs + (qw + 0) * 132);
            const ulonglong2* qB  = (const ulonglong2*)(Qs + (qw + 1) * 132);
#pragma unroll
            for (int h = 0; h < 4; h++) {
                unsigned long long a00 = 0, a01 = 0, a10 = 0, a11 = 0;
#pragma unroll
                for (int u = 0; u < 8; u++) {
                    const ulonglong2 k0 = kR0[h * 8 + u];
                    const ulonglong2 k1 = kR1[h * 8 + u];
                    const ulonglong2 qa = qA[h * 8 + u];
                    const ulonglong2 qb = qB[h * 8 + u];
                    fma2(a00, qa.x, k0.x); fma2(a00, qa.y, k0.y);
                    fma2(a01, qa.x, k1.x); fma2(a01, qa.y, k1.y);
                    fma2(a10, qb.x, k0.x); fma2(a10, qb.y, k0.y);
                    fma2(a11, qb.x, k1.x); fma2(a11, qb.y, k1.y);
                }
                float x, y;
                unpack2(a00, x, y); s0[0][h] = x + y;
                unpack2(a01, x, y); s1[0][h] = x + y;
                unpack2(a10, x, y); s0[1][h] = x + y;
                unpack2(a11, x, y); s1[1][h] = x + y;
            }
        }

        // ---- MLP, packed over the lane's (p0,p1) pair ----
        float y0[2][4], y1[2][4];
#pragma unroll
        for (int q = 0; q < 2; q++) {
            unsigned long long x2[8];
#pragma unroll
            for (int h = 0; h < 4; h++) {
                x2[h]     = pack2(s0[q][h], s1[q][h]);
                x2[4 + h] = o2[q][h];
            }
            unsigned long long hid[8];
#pragma unroll
            for (int j = 0; j < 8; j++) {
                unsigned long long z = wtU[64 + j];
#pragma unroll
                for (int i = 0; i < 8; i++) fma2(z, wtU[j * 8 + i], x2[i]);
                float zl, zh; unpack2(z, zl, zh);
                hid[j] = pack2(fmaxf(zl, 0.f), fmaxf(zh, 0.f));
            }
#pragma unroll
            for (int h = 0; h < 4; h++) {
                unsigned long long z = wtU[104 + h];
#pragma unroll
                for (int j = 0; j < 8; j++) fma2(z, wtU[72 + h * 8 + j], hid[j]);
                unpack2(z, y0[q][h], y1[q][h]);
            }
        }

        // ---- online softmax; store packed exp-weights ----
#pragma unroll
        for (int q = 0; q < 2; q++) {
#pragma unroll
            for (int h = 0; h < 4; h++) {
                const float ya = y0[q][h], yb = y1[q][h];
                float mx = fmaxf(ya, yb);
#pragma unroll
                for (int off = 16; off; off >>= 1)
                    mx = fmaxf(mx, __shfl_xor_sync(0xffffffffu, mx, off));
                const float mo = m[q][h];
                const float mn = fmaxf(mo, mx);
                if (mn > mo) {                       // warp-uniform branch
                    const float corr = __expf(mo - mn);
                    l[q][h] *= corr;
                    mul2(acc[q][h], pack2(corr, corr));
                    m[q][h] = mn;
                }
                const float wa = __expf(ya - mn);
                const float wb = __expf(yb - mn);
                float ts = wa + wb;
#pragma unroll
                for (int off = 16; off; off >>= 1)
                    ts += __shfl_xor_sync(0xffffffffu, ts, off);
                l[q][h] += ts;
                wsU[(q * 4 + h) * 32 + lane] = pack2(wa, wb);
            }
        }
        __syncwarp();

        // ---- AV: lane = v; packed over p-pairs ----
#pragma unroll
        for (int h = 0; h < 4; h++) {
            const ulonglong2* vR = (const ulonglong2*)(Vt + (h * 32 + lane) * 68);
            const ulonglong2* wA = (const ulonglong2*)(wsU + (0 * 4 + h) * 32);
            const ulonglong2* wB = (const ulonglong2*)(wsU + (1 * 4 + h) * 32);
            unsigned long long A0 = acc[0][h], A1 = acc[1][h];
#pragma unroll
            for (int jg = 0; jg < 16; jg++) {
                const ulonglong2 v2 = vR[jg];
                const ulonglong2 wa = wA[jg];
                const ulonglong2 wb = wB[jg];
                fma2(A0, wa.x, v2.x); fma2(A0, wa.y, v2.y);
                fma2(A1, wb.x, v2.x); fma2(A1, wb.y, v2.y);
            }
            acc[0][h] = A0; acc[1][h] = A1;
        }
        __syncwarp();
    }

    // ---- epilogue ----
#pragma unroll
    for (int q = 0; q < 2; q++) {
        const int qg = q0 + qw + q;
#pragma unroll
        for (int h = 0; h < 4; h++) {
            float x, y; unpack2(acc[q][h], x, y);
            g_heads[(size_t)(b * GG + qg) * 128 + h * 32 + lane] = (x + y) / l[q][h];
        }
    }
}

// =============================================================================
// K2: out[b,q,e] = sum_t heads[b,q,t] * Wout[t,e]
// =============================================================================
__global__ void outproj_kernel(const float* __restrict__ Wout,
                               float* __restrict__ out)
{
    __shared__ float hs[8 * 128];
    const int tid  = threadIdx.x;
    const int row0 = blockIdx.x * 8;

    for (int idx = tid; idx < 8 * 128; idx += 128)
        hs[idx] = g_heads[(size_t)row0 * 128 + idx];
    __syncthreads();

    float a[8];
#pragma unroll
    for (int r = 0; r < 8; r++) a[r] = 0.f;

    for (int t = 0; t < 128; t++) {
        const float w = __ldg(Wout + t * 128 + tid);
#pragma unroll
        for (int r = 0; r < 8; r++) a[r] += hs[r * 128 + t] * w;
    }
#pragma unroll
    for (int r = 0; r < 8; r++)
        out[(size_t)(row0 + r) * 128 + tid] = a[r];
}

// =============================================================================
extern "C" void kernel_launch(void* const* d_in, const int* in_sizes, int n_in,
                              void* d_out, int out_size)
{
    const float* hin  = (const float*)d_in[0];
    const float* osa  = (const float*)d_in[1];
    const float* Wq   = (const float*)d_in[2];
    const float* Wk   = (const float*)d_in[3];
    const float* Wv   = (const float*)d_in[4];
    const float* Wout = (const float*)d_in[5];
    const float* w1   = (const float*)d_in[6];
    const float* b1   = (const float*)d_in[7];
    const float* w2   = (const float*)d_in[8];
    const float* b2   = (const float*)d_in[9];
    (void)in_sizes; (void)n_in;

    float* out = (float*)d_out;

    const int OUT_ELEMS = BB * GG * EE;
    const long long OSA_ELEMS = (long long)HH * BB * GG * GG;
    const int doCopy = ((long long)out_size >= OUT_ELEMS + OSA_ELEMS) ? 1 : 0;
    float* osaCopy = doCopy ? (out + OUT_ELEMS) : out;

    cudaFuncSetAttribute(attn_kernel,
                         cudaFuncAttributeMaxDynamicSharedMemorySize, SMEM_BYTES);

    qkv_kernel<<<BB * GG / 16, 256>>>(hin, Wq, Wk, Wv);
    attn_kernel<<<dim3(GG / TQ, BB), NT, SMEM_BYTES>>>(
        osa, w1, b1, w2, b2, osaCopy, doCopy);
    outproj_kernel<<<BB * GG / 8, 128>>>(Wout, out);
}

// round 9
// speedup vs baseline: 1.0805x; 1.0297x over previous
#include <cuda_runtime.h>
#include <cuda_bf16.h>
#include <cstdint>

#define BB 2
#define GG 2048
#define HH 4
#define EE 128

#define TQ 16      // q rows per block
#define TP 64      // p columns per tile
#define PSPLIT 2   // p-range splits
#define PRANGE (GG / PSPLIT)      // 1024
#define NTILE (PRANGE / TP)       // 16
#define NT 256     // threads per attn block (8 warps)

// ---------------- device scratch ----------------
__device__ float g_Q[BB * GG * 128];      // [b][g][h*32+k]
__device__ float g_K[BB * GG * 128];      // [b][g][h*32+k]
__device__ float g_Vt[BB * 128 * GG];     // transposed: [b][h*32+v][g]
__device__ float g_pacc[PSPLIT][BB * GG * 128];  // unnormalized AV partials
__device__ float g_pm[PSPLIT][BB * GG * 4];      // running max per (row,h)
__device__ float g_pl[PSPLIT][BB * GG * 4];      // softmax denom partial

// ---------------- f32x2 helpers ----------------
__device__ __forceinline__ unsigned long long pack2(float a, float b) {
    unsigned long long r;
    asm("mov.b64 %0, {%1, %2};" : "=l"(r) : "f"(a), "f"(b));
    return r;
}
__device__ __forceinline__ void unpack2(unsigned long long v, float& a, float& b) {
    asm("mov.b64 {%0, %1}, %2;" : "=f"(a), "=f"(b) : "l"(v));
}
__device__ __forceinline__ void fma2(unsigned long long& d,
                                     unsigned long long a, unsigned long long b) {
    asm("fma.rn.f32x2 %0, %1, %2, %0;" : "+l"(d) : "l"(a), "l"(b));
}
__device__ __forceinline__ void mul2(unsigned long long& d, unsigned long long a) {
    asm("mul.rn.f32x2 %0, %0, %1;" : "+l"(d) : "l"(a));
}

#define CP_ASYNC16(dst, src) \
    asm volatile("cp.async.cg.shared.global [%0], [%1], 16;" :: "r"(dst), "l"(src))
#define CP_COMMIT() asm volatile("cp.async.commit_group;" ::: "memory")
#define CP_WAIT0()  asm volatile("cp.async.wait_group 0;" ::: "memory")

// =============================================================================
// K0: fused QKV projection; V written globally transposed (d-major).
// grid = 512 blocks x 8 rows, 256 threads; d-loop unrolled x4 for MLP.
// =============================================================================
__global__ __launch_bounds__(256)
void qkv_kernel(const float* __restrict__ hin,
                const float* __restrict__ Wq,
                const float* __restrict__ Wk,
                const float* __restrict__ Wv)
{
    __shared__ float hs[8 * 128];
    const int tid  = threadIdx.x;
    const int row0 = blockIdx.x * 8;

    for (int i = tid; i < 8 * 128; i += 256)
        hs[i] = hin[(size_t)row0 * 128 + i];
    __syncthreads();

    const int sub   = tid >> 7;       // 0/1 -> rows 0-3 / 4-7
    const int col   = tid & 127;
    const int rbase = sub * 4;

    float aq[4], ak[4], av[4];
#pragma unroll
    for (int r = 0; r < 4; r++) { aq[r] = 0.f; ak[r] = 0.f; av[r] = 0.f; }

    const int hh = col >> 5, k = col & 31;
    const float* wqp = Wq + hh * 128 * 32 + k;
    const float* wkp = Wk + hh * 128 * 32 + k;
    const float* wvp = Wv + hh * 128 * 32 + k;

    for (int d = 0; d < 128; d += 4) {
        float wq[4], wk4[4], wv[4];
#pragma unroll
        for (int u = 0; u < 4; u++) {
            wq[u]  = __ldg(wqp + (d + u) * 32);
            wk4[u] = __ldg(wkp + (d + u) * 32);
            wv[u]  = __ldg(wvp + (d + u) * 32);
        }
#pragma unroll
        for (int u = 0; u < 4; u++) {
#pragma unroll
            for (int r = 0; r < 4; r++) {
                const float hv = hs[(rbase + r) * 128 + d + u];
                aq[r] += hv * wq[u];
                ak[r] += hv * wk4[u];
                av[r] += hv * wv[u];
            }
        }
    }

    const int growbase = row0 + rbase;
    const int b = growbase >> 11;     // 8 | 2048 -> no batch straddle
#pragma unroll
    for (int r = 0; r < 4; r++) {
        const int grow = growbase + r;
        const int g    = grow & 2047;
        g_Q[(size_t)grow * 128 + col] = aq[r];
        g_K[(size_t)grow * 128 + col] = ak[r];
        g_Vt[((size_t)(b * 128 + col)) * 2048 + g] = av[r];
    }
}

// =============================================================================
// K1: fused scores + MLP + online softmax + A@V partials (+ osa pass-through)
// grid = (128 qtiles, 2 batch, 2 psplit) = 512 blocks, 256 thr = 8 warps.
// Warp owns 2 q rows; lane owns p-pair (2*lane, 2*lane+1) of the 64-wide tile.
// Single-buffered cp.async staging; exp-weight buffer OVERLAYS the K tile
// (K fully consumed before the overlay write; guarded by a barrier).
// smem = 77,920 B -> 2 blocks/SM co-resident.
// =============================================================================
#define SM_QS 0                 /* 16 x 132            = 2112 floats */
#define SM_K  2112              /* 64 x 132            = 8448 floats */
#define SM_V  10560             /* 128 x 68            = 8704 floats */
#define SM_WT 19264             /* 108 ull             = 216 floats  */
#define SMEM_FLOATS 19480
#define SMEM_BYTES (SMEM_FLOATS * 4)

__global__ __launch_bounds__(NT, 2)
void attn_kernel(const float* __restrict__ osa,
                 const float* __restrict__ w1,
                 const float* __restrict__ b1,
                 const float* __restrict__ w2,
                 const float* __restrict__ b2,
                 float* __restrict__ osaCopy,
                 int doCopy)
{
    extern __shared__ float sm[];
    const uint32_t smaddr = (uint32_t)__cvta_generic_to_shared(sm);

    float* Qs = sm + SM_QS;
    unsigned long long* wtU = (unsigned long long*)(sm + SM_WT);

    const int tid  = threadIdx.x;
    const int warp = tid >> 5;
    const int lane = tid & 31;
    const int b    = blockIdx.y;
    const int ps   = blockIdx.z;
    const int q0   = blockIdx.x * TQ;
    const int qw   = warp * 2;
    const int p00  = ps * PRANGE;

    // exp-weight staging overlays the K tile region (per-warp 2 KB slice)
    unsigned long long* wsU = (unsigned long long*)(sm + SM_K) + warp * 256;

    // MLP weights, pre-duplicated {w,w}
    if (tid < 108) {
        float v;
        if (tid < 64)       v = __ldg(w1 + tid);
        else if (tid < 72)  v = __ldg(b1 + tid - 64);
        else if (tid < 104) v = __ldg(w2 + tid - 72);
        else                v = __ldg(b2 + tid - 104);
        wtU[tid] = pack2(v, v);
    }

    // Q tile: 16 rows x 128 floats, stride 132
#pragma unroll
    for (int j = 0; j < 2; j++) {
        const int c  = tid + j * 256;      // 0..511 (16 rows x 32 chunks)
        const int r  = c >> 5;
        const int cg = c & 31;
        ((float4*)(Qs + r * 132))[cg] =
            __ldg((const float4*)(g_Q + (size_t)(b * GG + q0 + r) * 128) + cg);
    }

    unsigned long long acc[2][4];           // packed over p-parity
    float m[2][4], lln[2][4];               // running max (warp-uniform), per-lane l
#pragma unroll
    for (int q = 0; q < 2; q++)
#pragma unroll
        for (int h = 0; h < 4; h++) { acc[q][h] = 0ULL; m[q][h] = -1e30f; lln[q][h] = 0.f; }

    for (int pt = 0; pt < NTILE; pt++) {
        const int pg0 = p00 + pt * TP;

        // ---- osa pair loads (in flight across barrier + staging) ----
        unsigned long long o2[2][4];
#pragma unroll
        for (int q = 0; q < 2; q++) {
            const int qg = q0 + qw + q;
#pragma unroll
            for (int h = 0; h < 4; h++) {
                const size_t idx = ((size_t)(h * BB + b) * GG + qg) * GG + pg0 + 2 * lane;
                o2[q][h] = __ldcs((const unsigned long long*)(osa + idx));
            }
        }

        __syncthreads();   // prev tile fully consumed (K/ws overlay + V free)

        // ---- stage K (row-permuted) and Vt, single-buffered ----
#pragma unroll
        for (int j = 0; j < 8; j++) {
            const int c   = tid + j * 256;        // 0..2047
            // K: 64 rows x 32 chunks; row p -> smem row (p>>1)+(p&1)*32
            const int kr  = c >> 5;
            const int kc  = (c & 31) * 4;
            const int pr  = (kr >> 1) + ((kr & 1) << 5);
            CP_ASYNC16(smaddr + (uint32_t)(SM_K + pr * 132 + kc) * 4u,
                       g_K + ((size_t)(b * GG + pg0 + kr)) * 128 + kc);
            // V: 128 rows x 16 chunks (d-major)
            const int vd  = c >> 4;
            const int vo  = (c & 15) * 4;
            CP_ASYNC16(smaddr + (uint32_t)(SM_V + vd * 68 + vo) * 4u,
                       g_Vt + ((size_t)(b * 128 + vd)) * 2048 + pg0 + vo);
        }
        CP_COMMIT();
        CP_WAIT0();
        __syncthreads();   // tile visible

        const float* Ks = sm + SM_K;
        const float* Vt = sm + SM_V;

        // ---- osa pass-through ----
        if (doCopy) {
#pragma unroll
            for (int q = 0; q < 2; q++) {
                const int qg = q0 + qw + q;
#pragma unroll
                for (int h = 0; h < 4; h++) {
                    const size_t idx = ((size_t)(h * BB + b) * GG + qg) * GG + pg0 + 2 * lane;
                    __stcs((unsigned long long*)(osaCopy + idx), o2[q][h]);
                }
            }
        }

        // ---- scores: packed over d-pairs; rows lane / lane+32 = p0 / p1 ----
        float s0[2][4], s1[2][4];
        {
            const ulonglong2* kR0 = (const ulonglong2*)(Ks + lane * 132);
            const ulonglong2* kR1 = (const ulonglong2*)(Ks + (lane + 32) * 132);
            const ulonglong2* qA  = (const ulonglong2*)(Qs + (qw + 0) * 132);
            const ulonglong2* qB  = (const ulonglong2*)(Qs + (qw + 1) * 132);
#pragma unroll
            for (int h = 0; h < 4; h++) {
                unsigned long long a00 = 0, a01 = 0, a10 = 0, a11 = 0;
#pragma unroll
                for (int u = 0; u < 8; u++) {
                    const ulonglong2 k0 = kR0[h * 8 + u];
                    const ulonglong2 k1 = kR1[h * 8 + u];
                    const ulonglong2 qa = qA[h * 8 + u];
                    const ulonglong2 qb = qB[h * 8 + u];
                    fma2(a00, qa.x, k0.x); fma2(a00, qa.y, k0.y);
                    fma2(a01, qa.x, k1.x); fma2(a01, qa.y, k1.y);
                    fma2(a10, qb.x, k0.x); fma2(a10, qb.y, k0.y);
                    fma2(a11, qb.x, k1.x); fma2(a11, qb.y, k1.y);
                }
                float x, y;
                unpack2(a00, x, y); s0[0][h] = x + y;
                unpack2(a01, x, y); s1[0][h] = x + y;
                unpack2(a10, x, y); s0[1][h] = x + y;
                unpack2(a11, x, y); s1[1][h] = x + y;
            }
        }

        // ---- MLP, packed over the lane's (p0,p1) pair ----
        float y0[2][4], y1[2][4];
#pragma unroll
        for (int q = 0; q < 2; q++) {
            unsigned long long x2[8];
#pragma unroll
            for (int h = 0; h < 4; h++) {
                x2[h]     = pack2(s0[q][h], s1[q][h]);
                x2[4 + h] = o2[q][h];
            }
            unsigned long long hid[8];
#pragma unroll
            for (int j = 0; j < 8; j++) {
                unsigned long long z = wtU[64 + j];
#pragma unroll
                for (int i = 0; i < 8; i++) fma2(z, wtU[j * 8 + i], x2[i]);
                float zl, zh; unpack2(z, zl, zh);
                hid[j] = pack2(fmaxf(zl, 0.f), fmaxf(zh, 0.f));
            }
#pragma unroll
            for (int h = 0; h < 4; h++) {
                unsigned long long z = wtU[104 + h];
#pragma unroll
                for (int j = 0; j < 8; j++) fma2(z, wtU[72 + h * 8 + j], hid[j]);
                unpack2(z, y0[q][h], y1[q][h]);
            }
        }

        __syncthreads();   // all warps done reading K -> ws overlay is safe

        // ---- online softmax: ballot-gated max update, per-lane l ----
        {
            bool need = false;
#pragma unroll
            for (int q = 0; q < 2; q++)
#pragma unroll
                for (int h = 0; h < 4; h++)
                    need |= (fmaxf(y0[q][h], y1[q][h]) > m[q][h]);

            if (__ballot_sync(0xffffffffu, need)) {
#pragma unroll
                for (int q = 0; q < 2; q++) {
#pragma unroll
                    for (int h = 0; h < 4; h++) {
                        float t = fmaxf(y0[q][h], y1[q][h]);
#pragma unroll
                        for (int off = 16; off; off >>= 1)
                            t = fmaxf(t, __shfl_xor_sync(0xffffffffu, t, off));
                        if (t > m[q][h]) {            // warp-uniform
                            const float corr = __expf(m[q][h] - t);
                            lln[q][h] *= corr;
                            mul2(acc[q][h], pack2(corr, corr));
                            m[q][h] = t;
                        }
                    }
                }
            }
#pragma unroll
            for (int q = 0; q < 2; q++) {
#pragma unroll
                for (int h = 0; h < 4; h++) {
                    const float wa = __expf(y0[q][h] - m[q][h]);
                    const float wb = __expf(y1[q][h] - m[q][h]);
                    lln[q][h] += wa + wb;
                    wsU[(q * 4 + h) * 32 + lane] = pack2(wa, wb);
                }
            }
        }
        __syncwarp();

        // ---- AV: lane = v; packed over p-pairs ----
#pragma unroll
        for (int h = 0; h < 4; h++) {
            const ulonglong2* vR = (const ulonglong2*)(Vt + (h * 32 + lane) * 68);
            const ulonglong2* wA = (const ulonglong2*)(wsU + (0 * 4 + h) * 32);
            const ulonglong2* wB = (const ulonglong2*)(wsU + (1 * 4 + h) * 32);
            unsigned long long A0 = acc[0][h], A1 = acc[1][h];
#pragma unroll
            for (int jg = 0; jg < 16; jg++) {
                const ulonglong2 v2 = vR[jg];
                const ulonglong2 wa = wA[jg];
                const ulonglong2 wb = wB[jg];
                fma2(A0, wa.x, v2.x); fma2(A0, wa.y, v2.y);
                fma2(A1, wb.x, v2.x); fma2(A1, wb.y, v2.y);
            }
            acc[0][h] = A0; acc[1][h] = A1;
        }
    }

    // ---- epilogue: store unnormalized partials + (m, l) ----
#pragma unroll
    for (int q = 0; q < 2; q++) {
        const int qg  = q0 + qw + q;
        const int row = b * GG + qg;
#pragma unroll
        for (int h = 0; h < 4; h++) {
            float ls = lln[q][h];
#pragma unroll
            for (int off = 16; off; off >>= 1)
                ls += __shfl_xor_sync(0xffffffffu, ls, off);
            if (lane == 0) {
                g_pm[ps][row * 4 + h] = m[q][h];
                g_pl[ps][row * 4 + h] = ls;
            }
            float x, y; unpack2(acc[q][h], x, y);
            g_pacc[ps][(size_t)row * 128 + h * 32 + lane] = x + y;
        }
    }
}

// =============================================================================
// K2: combine p-split partials + output projection.
// out[row,e] = sum_t head[row,t] * Wout[t,e],
// head[row,h*32+v] = (a0*e^{m0-M} + a1*e^{m1-M}) / (l0*e^{m0-M} + l1*e^{m1-M})
// =============================================================================
__global__ __launch_bounds__(128)
void outproj_kernel(const float* __restrict__ Wout,
                    float* __restrict__ out)
{
    __shared__ float hs[8 * 128];
    __shared__ float fc[8][4][2];
    const int tid  = threadIdx.x;
    const int row0 = blockIdx.x * 8;

    if (tid < 32) {
        const int r = tid >> 2, h = tid & 3;
        const int idx = (row0 + r) * 4 + h;
        const float m0 = g_pm[0][idx], m1 = g_pm[1][idx];
        const float l0 = g_pl[0][idx], l1 = g_pl[1][idx];
        const float M  = fmaxf(m0, m1);
        const float e0 = __expf(m0 - M), e1 = __expf(m1 - M);
        const float L  = l0 * e0 + l1 * e1;
        fc[r][h][0] = e0 / L;
        fc[r][h][1] = e1 / L;
    }
    __syncthreads();

    for (int i = tid; i < 8 * 128; i += 128) {
        const int r = i >> 7, c = i & 127, h = c >> 5;
        hs[i] = g_pacc[0][(size_t)(row0 + r) * 128 + c] * fc[r][h][0]
              + g_pacc[1][(size_t)(row0 + r) * 128 + c] * fc[r][h][1];
    }
    __syncthreads();

    float a[8];
#pragma unroll
    for (int r = 0; r < 8; r++) a[r] = 0.f;

    for (int t = 0; t < 128; t += 4) {
        float w[4];
#pragma unroll
        for (int u = 0; u < 4; u++) w[u] = __ldg(Wout + (t + u) * 128 + tid);
#pragma unroll
        for (int u = 0; u < 4; u++)
#pragma unroll
            for (int r = 0; r < 8; r++) a[r] += hs[r * 128 + t + u] * w[u];
    }
#pragma unroll
    for (int r = 0; r < 8; r++)
        out[(size_t)(row0 + r) * 128 + tid] = a[r];
}

// =============================================================================
extern "C" void kernel_launch(void* const* d_in, const int* in_sizes, int n_in,
                              void* d_out, int out_size)
{
    const float* hin  = (const float*)d_in[0];
    const float* osa  = (const float*)d_in[1];
    const float* Wq   = (const float*)d_in[2];
    const float* Wk   = (const float*)d_in[3];
    const float* Wv   = (const float*)d_in[4];
    const float* Wout = (const float*)d_in[5];
    const float* w1   = (const float*)d_in[6];
    const float* b1   = (const float*)d_in[7];
    const float* w2   = (const float*)d_in[8];
    const float* b2   = (const float*)d_in[9];
    (void)in_sizes; (void)n_in;

    float* out = (float*)d_out;

    const int OUT_ELEMS = BB * GG * EE;
    const long long OSA_ELEMS = (long long)HH * BB * GG * GG;
    const int doCopy = ((long long)out_size >= OUT_ELEMS + OSA_ELEMS) ? 1 : 0;
    float* osaCopy = doCopy ? (out + OUT_ELEMS) : out;

    cudaFuncSetAttribute(attn_kernel,
                         cudaFuncAttributeMaxDynamicSharedMemorySize, SMEM_BYTES);

    qkv_kernel<<<BB * GG / 8, 256>>>(hin, Wq, Wk, Wv);
    attn_kernel<<<dim3(GG / TQ, BB, PSPLIT), NT, SMEM_BYTES>>>(
        osa, w1, b1, w2, b2, osaCopy, doCopy);
    outproj_kernel<<<BB * GG / 8, 128>>>(Wout, out);
}